// round 1
// baseline (speedup 1.0000x reference)
#include <cuda_runtime.h>
#include <math.h>

#define B 4
#define S 4096
#define H 8
#define D 64
#define HD 512            // H*D
#define ROWS (B*S*H)      // 131072
#define NBS (B*S)         // 16384
#define NC 64             // chunks for cumsum
#define LC (S/NC)         // 64
#define NC2 64            // chunks for lstm scan
#define LC2 (S/NC2)       // 64
#define LN_EPS 1e-5f

// ---- scratch (device globals; no allocation allowed) ----
__device__ float g_csum[(size_t)B*S*HD];
__device__ float g_fg[(size_t)B*S*HD];
__device__ float g_igh[(size_t)B*S*HD];
__device__ float g_cell[(size_t)B*S*HD];
__device__ float g_chunksum[(size_t)B*NC*HD];
__device__ float g_chunkpref[(size_t)B*NC*HD];
__device__ float g_mean[NBS];
__device__ float g_rstd[NBS];
__device__ float g_sA[(size_t)B*NC2*HD];
__device__ float g_sB[(size_t)B*NC2*HD];
__device__ float g_cellin[(size_t)B*NC2*HD];

// ---------------- cumsum phase 1: per-chunk sums ----------------
__global__ void k_chunksum(const float* __restrict__ x) {
    int blk = blockIdx.x;              // b*NC + c
    int b = blk / NC, c = blk % NC;
    int t = threadIdx.x;               // 0..511 = (h,d)
    const float* p = x + ((size_t)(b*S + c*LC))*HD + t;
    float s = 0.f;
    #pragma unroll 8
    for (int i = 0; i < LC; ++i) s += p[(size_t)i*HD];
    g_chunksum[(size_t)blk*HD + t] = s;
}

// ---------------- cumsum phase 2: exclusive scan of chunk sums ----------------
__global__ void k_chunkscan() {
    int b = blockIdx.x; int t = threadIdx.x;
    float run = 0.f;
    for (int c = 0; c < NC; ++c) {
        size_t i = ((size_t)(b*NC + c))*HD + t;
        g_chunkpref[i] = run;
        run += g_chunksum[i];
    }
}

// ---------------- cumsum phase 3: write exclusive cumsum ----------------
__global__ void k_csum(const float* __restrict__ x) {
    int blk = blockIdx.x; int b = blk/NC, c = blk%NC; int t = threadIdx.x;
    float run = g_chunkpref[(size_t)blk*HD + t];
    size_t base = ((size_t)(b*S + c*LC))*HD + t;
    #pragma unroll 4
    for (int i = 0; i < LC; ++i) {
        size_t idx = base + (size_t)i*HD;
        g_csum[idx] = run;      // exclusive: value BEFORE adding x[s]
        run += x[idx];
    }
}

// ---------------- LayerNorm stats over (H,D)=512 per (b,s) ----------------
__global__ void k_lnstats() {
    int row = blockIdx.x; int t = threadIdx.x;
    float v = g_csum[(size_t)row*HD + t];
    float s = v, q = v*v;
    #pragma unroll
    for (int o = 16; o; o >>= 1) {
        s += __shfl_down_sync(0xFFFFFFFFu, s, o);
        q += __shfl_down_sync(0xFFFFFFFFu, q, o);
    }
    __shared__ float ss[16], sq[16];
    int w = t >> 5, l = t & 31;
    if (l == 0) { ss[w] = s; sq[w] = q; }
    __syncthreads();
    if (t < 32) {
        s = (t < 16) ? ss[t] : 0.f;
        q = (t < 16) ? sq[t] : 0.f;
        #pragma unroll
        for (int o = 8; o; o >>= 1) {
            s += __shfl_down_sync(0xFFFFFFFFu, s, o);
            q += __shfl_down_sync(0xFFFFFFFFu, q, o);
        }
        if (t == 0) {
            float m = s * (1.f/HD);
            float var = q * (1.f/HD) - m*m;
            g_mean[row] = m;
            g_rstd[row] = rsqrtf(var + LN_EPS);
        }
    }
}

__device__ __forceinline__ float sigmoidf_(float v) {
    return 1.f / (1.f + __expf(-v));
}

// ---------------- GEMM1: [ROWS,128] @ W_hid[128,192] + gates ----------------
// 768 threads = 192 cols x 4 K-quarters. W in registers (32/thread).
#define R1 8
__global__ void __launch_bounds__(768, 1)
k_gemm1(const float* __restrict__ x, const float* __restrict__ Wh,
        const float* __restrict__ bh, const float* __restrict__ gamma,
        const float* __restrict__ beta) {
    __shared__ float hid[R1][128];
    __shared__ float part[4][R1][192];
    __shared__ float h3[R1][192];
    __shared__ float sb[192];
    __shared__ float sg[512], sbe[512];
    int t = threadIdx.x;
    int j = t % 192, kq = t / 192;
    float w[32];
    #pragma unroll
    for (int k = 0; k < 32; ++k) w[k] = Wh[(size_t)(kq*32 + k)*192 + j];
    if (t < 192) sb[t] = bh[t];
    if (t < 512) { sg[t] = gamma[t]; sbe[t] = beta[t]; }
    __syncthreads();

    for (int g = blockIdx.x; g < ROWS/R1; g += gridDim.x) {
        int row0 = g * R1;
        // stage 8 rows of hid_in = concat(x, LN(csum))
        for (int v = t; v < R1*128; v += 768) {
            int r = v >> 7, p = v & 127;
            int ri = row0 + r;
            float val;
            if (p < 64) {
                val = x[(size_t)ri*64 + p];
            } else {
                int d = p - 64;
                int h = ri & (H-1);
                int bs = ri >> 3;            // ri / H
                float c = g_csum[(size_t)ri*64 + d];
                val = (c - g_mean[bs]) * g_rstd[bs] * sg[h*64 + d] + sbe[h*64 + d];
            }
            hid[r][p] = val;
        }
        __syncthreads();
        float acc[R1];
        #pragma unroll
        for (int r = 0; r < R1; ++r) {
            float a = 0.f;
            const float4* hp = (const float4*)&hid[r][kq*32];
            #pragma unroll
            for (int k4 = 0; k4 < 8; ++k4) {
                float4 hv = hp[k4];
                a += hv.x * w[k4*4+0];
                a += hv.y * w[k4*4+1];
                a += hv.z * w[k4*4+2];
                a += hv.w * w[k4*4+3];
            }
            acc[r] = a;
        }
        #pragma unroll
        for (int r = 0; r < R1; ++r) part[kq][r][j] = acc[r];
        __syncthreads();
        // combine K-quarters + bias
        for (int v = t; v < R1*192; v += 768) {
            int r = v / 192, jj = v % 192;
            h3[r][jj] = part[0][r][jj] + part[1][r][jj] +
                        part[2][r][jj] + part[3][r][jj] + sb[jj];
        }
        __syncthreads();
        // gates: igate [0,64), fgate [64,128), hidden [128,192)
        if (t < R1*64) {
            int r = t >> 6, d = t & 63;
            float ig = h3[r][d], fgv = h3[r][64+d], hv = h3[r][128+d];
            size_t o = (size_t)(row0 + r)*64 + d;
            g_fg[o]  = sigmoidf_(fgv);
            g_igh[o] = sigmoidf_(ig) * fmaxf(hv, 0.f);
        }
        __syncthreads();
    }
}

// ---------------- LSTM chunked scan ----------------
__global__ void k_lstm_chunk() {
    int blk = blockIdx.x; int t = threadIdx.x;
    int b = blk / NC2, c = blk % NC2;
    size_t base = ((size_t)(b*S + c*LC2))*HD + t;
    float A = 1.f, Bv = 0.f;
    #pragma unroll 4
    for (int i = 0; i < LC2; ++i) {
        size_t idx = base + (size_t)i*HD;
        float f  = g_fg[idx];
        float ig = g_igh[idx];
        Bv = f*Bv + ig;
        A  = f*A;
    }
    g_sA[(size_t)blk*HD + t] = A;
    g_sB[(size_t)blk*HD + t] = Bv;
}

__global__ void k_lstm_scan(const float* __restrict__ init_cx) {
    int b = blockIdx.x; int t = threadIdx.x;
    float cell = init_cx[t];          // init_cx is [H,D] = 512, t == h*64+d
    for (int c = 0; c < NC2; ++c) {
        size_t i = ((size_t)(b*NC2 + c))*HD + t;
        g_cellin[i] = cell;
        cell = g_sA[i]*cell + g_sB[i];
    }
}

__global__ void k_cell() {
    int blk = blockIdx.x; int t = threadIdx.x;
    int b = blk / NC2, c = blk % NC2;
    float cell = g_cellin[(size_t)blk*HD + t];
    size_t base = ((size_t)(b*S + c*LC2))*HD + t;
    #pragma unroll 4
    for (int i = 0; i < LC2; ++i) {
        size_t idx = base + (size_t)i*HD;
        cell = g_fg[idx]*cell + g_igh[idx];
        g_cell[idx] = cell;
    }
}

// ---------------- GEMM2: [ROWS,128] @ W_og[128,64], sigmoid * cell ----------------
#define R2 8
__global__ void __launch_bounds__(256)
k_gemm2(const float* __restrict__ x, const float* __restrict__ Wo,
        const float* __restrict__ bo, float* __restrict__ out) {
    __shared__ float hid[R2][128];
    __shared__ float part[4][R2][64];
    __shared__ float sb[64];
    int t = threadIdx.x;
    int j = t & 63, kq = t >> 6;
    float w[32];
    #pragma unroll
    for (int k = 0; k < 32; ++k) w[k] = Wo[(size_t)(kq*32 + k)*64 + j];
    if (t < 64) sb[t] = bo[t];
    __syncthreads();

    for (int g = blockIdx.x; g < ROWS/R2; g += gridDim.x) {
        int row0 = g * R2;
        for (int v = t; v < R2*128; v += 256) {
            int r = v >> 7, p = v & 127;
            int ri = row0 + r;
            hid[r][p] = (p < 64) ? x[(size_t)ri*64 + p]
                                 : g_cell[(size_t)ri*64 + (p - 64)];
        }
        __syncthreads();
        #pragma unroll
        for (int r = 0; r < R2; ++r) {
            float a = 0.f;
            const float4* hp = (const float4*)&hid[r][kq*32];
            #pragma unroll
            for (int k4 = 0; k4 < 8; ++k4) {
                float4 hv = hp[k4];
                a += hv.x * w[k4*4+0];
                a += hv.y * w[k4*4+1];
                a += hv.z * w[k4*4+2];
                a += hv.w * w[k4*4+3];
            }
            part[kq][r][j] = a;
        }
        __syncthreads();
        for (int v = t; v < R2*64; v += 256) {
            int r = v >> 6, jj = v & 63;
            float sum = part[0][r][jj] + part[1][r][jj] +
                        part[2][r][jj] + part[3][r][jj] + sb[jj];
            float og = sigmoidf_(sum);
            float cv = hid[r][64 + jj];
            out[(size_t)(row0 + r)*64 + jj] = og * cv;
        }
        __syncthreads();
    }
}

extern "C" void kernel_launch(void* const* d_in, const int* in_sizes, int n_in,
                              void* d_out, int out_size) {
    const float* x     = (const float*)d_in[0];   // heads_input [B,S,H,D]
    const float* Wh    = (const float*)d_in[1];   // W_hid [128,192]
    const float* bh    = (const float*)d_in[2];   // b_hid [192]
    const float* Wo    = (const float*)d_in[3];   // W_og [128,64]
    const float* bo    = (const float*)d_in[4];   // b_og [64]
    const float* gamma = (const float*)d_in[5];   // ln_gamma [H,D]
    const float* beta  = (const float*)d_in[6];   // ln_beta [H,D]
    const float* cx    = (const float*)d_in[7];   // init_cx [H,D]
    float* out = (float*)d_out;

    k_chunksum<<<B*NC, 512>>>(x);
    k_chunkscan<<<B, 512>>>();
    k_csum<<<B*NC, 512>>>(x);
    k_lnstats<<<NBS, 512>>>();
    k_gemm1<<<148, 768>>>(x, Wh, bh, gamma, beta);
    k_lstm_chunk<<<B*NC2, 512>>>();
    k_lstm_scan<<<B, 512>>>(cx);
    k_cell<<<B*NC2, 512>>>();
    k_gemm2<<<592, 256>>>(x, Wo, bo, out);
}